// round 9
// baseline (speedup 1.0000x reference)
#include <cuda_runtime.h>
#include <cuda_fp16.h>
#include <cstdint>

// ---------------------------------------------------------------------------
// B=32, CIN=256, COUT=256, 64x64 -> 32x32, 3x3 stride2 pad1 conv. Crop mask
// all-True => plain conv. fp16 m16n8k16 two-term split GEMM:
//   C = Ahi*Bhi + Alo*Bhi   (weights split hi/lo fp16, x single fp16)
// Round 9: full/empty mbarrier pipeline, NO per-iter __syncthreads.
// ---------------------------------------------------------------------------

#define B_    32
#define CIN_  256
#define COUT_ 256
#define H_    64
#define W_    64
#define HW_   4096
#define NPIX_ 1024

#define BM 128
#define BN 256
#define KC 64
#define NIT 36                 // 9 taps * 4 cin-chunks

#define ROW_B    144
#define AH_OFF   0
#define AL_OFF   (128 * ROW_B)             // 18432
#define B_OFF2   (2 * 128 * ROW_B)         // 36864
#define STAGE_B  (B_OFF2 + 256 * ROW_B)    // 73728
#define TILES_OFF 1024
#define NSTAGE   3
#define SMEM_TOTAL (TILES_OFF + NSTAGE * STAGE_B)   // 222208

__device__ __align__(128) __half g_Ah[9 * COUT_ * CIN_];        // [p][cout][cin]
__device__ __align__(128) __half g_Al[9 * COUT_ * CIN_];
__device__ __align__(128) __half g_X[(size_t)B_ * HW_ * CIN_];  // [b][s][cin]

// ---------------------------------------------------------------------------
__device__ __forceinline__ uint32_t smem_u32(const void* p) {
    uint32_t a;
    asm("{ .reg .u64 t; cvta.to.shared.u64 t, %1; cvt.u32.u64 %0, t; }" : "=r"(a) : "l"(p));
    return a;
}
__device__ __forceinline__ void bulk_g2s(uint32_t dst, const void* src, uint32_t bytes,
                                         uint32_t mbar) {
    asm volatile(
        "cp.async.bulk.shared::cluster.global.mbarrier::complete_tx::bytes "
        "[%0], [%1], %2, [%3];"
        :: "r"(dst), "l"(src), "r"(bytes), "r"(mbar) : "memory");
}
__device__ __forceinline__ void mbar_init(uint32_t a, uint32_t cnt) {
    asm volatile("mbarrier.init.shared.b64 [%0], %1;" :: "r"(a), "r"(cnt) : "memory");
}
__device__ __forceinline__ void mbar_arrive(uint32_t a) {
    asm volatile("mbarrier.arrive.release.cta.shared::cta.b64 _, [%0];"
                 :: "r"(a) : "memory");
}
__device__ __forceinline__ void mbar_expect_tx(uint32_t a, uint32_t tx) {
    asm volatile("mbarrier.arrive.expect_tx.shared.b64 _, [%0], %1;"
                 :: "r"(a), "r"(tx) : "memory");
}
__device__ __forceinline__ void mbar_wait(uint32_t a, uint32_t parity) {
    asm volatile(
        "{\n\t.reg .pred P1;\n\t"
        "W_%=:\n\t"
        "mbarrier.try_wait.parity.acquire.cta.shared::cta.b64 P1, [%0], %1, 0x989680;\n\t"
        "@!P1 bra W_%=;\n\t}"
        :: "r"(a), "r"(parity) : "memory");
}
__device__ __forceinline__ void mma_fp16(float* d, const uint32_t* a, uint32_t b0, uint32_t b1) {
    asm volatile(
        "mma.sync.aligned.m16n8k16.row.col.f32.f16.f16.f32 "
        "{%0,%1,%2,%3}, {%4,%5,%6,%7}, {%8,%9}, {%0,%1,%2,%3};"
        : "+f"(d[0]), "+f"(d[1]), "+f"(d[2]), "+f"(d[3])
        : "r"(a[0]), "r"(a[1]), "r"(a[2]), "r"(a[3]), "r"(b0), "r"(b1));
}
__device__ __forceinline__ void ldm4(uint32_t* r, uint32_t addr) {
    asm volatile("ldmatrix.sync.aligned.m8n8.x4.shared.b16 {%0,%1,%2,%3}, [%4];"
                 : "=r"(r[0]), "=r"(r[1]), "=r"(r[2]), "=r"(r[3]) : "r"(addr));
}

// ---------------------------------------------------------------------------
// Fused prologue: blocks [0, 2304) -> weight split; [2304, 35072) -> x convert
// ---------------------------------------------------------------------------
__global__ void transform_kernel(const float* __restrict__ x, const float* __restrict__ w) {
    __shared__ float tile[32][33];   // tile[c_local][s_local]
    const int tid = threadIdx.x;
    if (blockIdx.x < 2304) {
        int idx = blockIdx.x * 256 + tid;           // over [p][cout][cin]
        int cin = idx & 255;
        int cout = (idx >> 8) & 255;
        int p = idx >> 16;
        float v = w[cout * (CIN_ * 9) + cin * 9 + p];
        __half hi = __float2half_rn(v);
        g_Ah[idx] = hi;
        g_Al[idx] = __float2half_rn(v - __half2float(hi));
        return;
    }
    const int t = blockIdx.x - 2304;
    const int s0 = (t & 127) * 32;
    const int c0 = ((t >> 7) & 7) * 32;
    const int b = t >> 10;
    const int tx = tid & 31, ty = tid >> 5;         // 32 x 8
    const float* xb = x + ((size_t)b * CIN_ + c0) * HW_ + s0;
#pragma unroll
    for (int k = 0; k < 4; ++k)
        tile[ty + 8 * k][tx] = xb[(size_t)(ty + 8 * k) * HW_ + tx];   // tile[c][s]
    __syncthreads();
    const int c2 = (tid & 15) * 2;
#pragma unroll
    for (int k = 0; k < 2; ++k) {
        const int s = (tid >> 4) + 16 * k;
        __half2 v = __floats2half2_rn(tile[c2][s], tile[c2 + 1][s]);
        size_t o = ((size_t)b * HW_ + s0 + s) * CIN_ + c0 + c2;
        *(__half2*)(g_X + o) = v;
    }
}

// ---------------------------------------------------------------------------
// Main fp16 implicit-GEMM. grid (2, 128), 512 threads (16 warps, 4/SMSP).
// Full/empty mbarrier pipeline, no per-iter CTA barrier.
// ---------------------------------------------------------------------------
__global__ void __launch_bounds__(512, 1) conv_fp16_kernel(float* __restrict__ out) {
    extern __shared__ char smem[];
    const uint32_t sb = smem_u32(smem);
    const int tid = threadIdx.x;
    const int lane = tid & 31, warp = tid >> 5;
    const int m0 = blockIdx.x * BM;
    const int n0 = blockIdx.y * BN;
    const int b = n0 >> 10;
    const int pix0 = n0 & (NPIX_ - 1);

    // full[s] at sb + s*16 (count 257); empty[s] at sb + 48 + s*16 (count 16)
    if (tid < NSTAGE) mbar_init(sb + tid * 16, 257);
    else if (tid < 2 * NSTAGE) mbar_init(sb + 48 + (tid - NSTAGE) * 16, 16);
    asm volatile("fence.proxy.async.shared::cta;" ::: "memory");
    __syncthreads();

    const int pixL = pix0 + (tid & 255);
    const int ohL = pixL >> 5, owL = pixL & 31;
    const __half* gX0 = g_X + (size_t)b * HW_ * CIN_;

    auto load_stage = [&](int buf, int s) {
        if (tid >= 256) return;
        const int p = s >> 2;
        const int cin0 = (s & 3) * KC;
        const int kh = p / 3, kw = p - kh * 3;
        const uint32_t st = sb + TILES_OFF + buf * STAGE_B;
        const uint32_t mb = sb + buf * 16;
        if (tid == 0) {
            int invalid = (kw == 0 ? 8 : 0)
                        + ((kh == 0 && pix0 == 0) ? 32 : 0)
                        - ((kw == 0 && kh == 0 && pix0 == 0) ? 1 : 0);
            uint32_t tx = 32768u + 128u * (uint32_t)(256 - invalid);
            mbar_expect_tx(mb, tx);
        }
        const int ar = tid & 127;
        const __half* srcA = ((tid < 128) ? g_Ah : g_Al)
                           + (size_t)p * (COUT_ * CIN_) + (size_t)(m0 + ar) * CIN_ + cin0;
        bulk_g2s(st + ((tid < 128) ? AH_OFF : AL_OFF) + ar * ROW_B, srcA, 128, mb);
        const int ih = ohL * 2 - 1 + kh;
        const int iw = owL * 2 - 1 + kw;
        const uint32_t dst = st + B_OFF2 + tid * ROW_B;
        if (((unsigned)ih < (unsigned)H_) && ((unsigned)iw < (unsigned)W_)) {
            bulk_g2s(dst, gX0 + (size_t)(ih * W_ + iw) * CIN_ + cin0, 128, mb);
        } else {
#pragma unroll
            for (int j = 0; j < 8; ++j)
                asm volatile("st.shared.v4.b32 [%0], {%1, %1, %1, %1};"
                             :: "r"(dst + j * 16), "r"(0u) : "memory");
        }
        mbar_arrive(mb);                   // release: orders zero-STS for consumers
    };

    float acc[2][8][4];
#pragma unroll
    for (int mi = 0; mi < 2; ++mi)
#pragma unroll
        for (int ni = 0; ni < 8; ++ni)
#pragma unroll
            for (int j = 0; j < 4; ++j) acc[mi][ni][j] = 0.0f;

    load_stage(0, 0);
    load_stage(1, 1);
    load_stage(2, 2);

    const int mw = (warp >> 2) * 32;      // 0,32,64,96
    const int nw = (warp & 3) * 64;       // 0,64,128,192
    uint32_t aOff[2], bOff[4];
#pragma unroll
    for (int mi = 0; mi < 2; ++mi)
        aOff[mi] = (uint32_t)((mw + mi * 16 + (lane & 15)) * ROW_B + (lane >> 4) * 16);
#pragma unroll
    for (int nj = 0; nj < 4; ++nj)
        bOff[nj] = (uint32_t)(B_OFF2
                 + (nw + nj * 16 + (lane & 7) + (lane >> 4) * 8) * ROW_B
                 + ((lane >> 3) & 1) * 16);

    int ib = 0;
    int phF[NSTAGE] = {0, 0, 0};
    int phE[NSTAGE] = {0, 0, 0};

#pragma unroll 1
    for (int it = 0; it < NIT; ++it) {
        mbar_wait(sb + ib * 16, phF[ib]);
        phF[ib] ^= 1;
        const uint32_t st = sb + TILES_OFF + ib * STAGE_B;
#pragma unroll
        for (int ks = 0; ks < 4; ++ks) {
            const uint32_t kb = (uint32_t)(ks * 32);
            uint32_t ah[2][4], al[2][4], bf[4][4];
#pragma unroll
            for (int mi = 0; mi < 2; ++mi) {
                ldm4(ah[mi], st + aOff[mi] + kb);
                ldm4(al[mi], st + AL_OFF + aOff[mi] + kb);
            }
#pragma unroll
            for (int nj = 0; nj < 4; ++nj)
                ldm4(bf[nj], st + bOff[nj] + kb);
#pragma unroll
            for (int nj = 0; nj < 4; ++nj)
#pragma unroll
                for (int s2 = 0; s2 < 2; ++s2) {
                    const int ni = nj * 2 + s2;
                    const uint32_t b0 = bf[nj][s2 * 2];
                    const uint32_t b1 = bf[nj][s2 * 2 + 1];
#pragma unroll
                    for (int mi = 0; mi < 2; ++mi) {
                        mma_fp16(acc[mi][ni], ah[mi], b0, b1);
                        mma_fp16(acc[mi][ni], al[mi], b0, b1);
                    }
                }
        }
        // MMA issue implies all ldmatrix results consumed -> stage free
        if (lane == 0) mbar_arrive(sb + 48 + ib * 16);
        if (it + NSTAGE < NIT) {
            if (tid < 256) mbar_wait(sb + 48 + ib * 16, phE[ib]);
            phE[ib] ^= 1;
            load_stage(ib, it + NSTAGE);
        }
        if (++ib == NSTAGE) ib = 0;
    }

    // ---- epilogue ----
    const int lg = lane >> 2;
    const int lc = lane & 3;
    float* ob = out + (size_t)b * COUT_ * NPIX_;
#pragma unroll
    for (int mi = 0; mi < 2; ++mi) {
        const int cout0 = m0 + mw + mi * 16 + lg;
#pragma unroll
        for (int ni = 0; ni < 8; ++ni) {
            const int nc = pix0 + nw + ni * 8 + lc * 2;
            float2* p0 = (float2*)(ob + (size_t)cout0 * NPIX_ + nc);
            float2* p1 = (float2*)(ob + (size_t)(cout0 + 8) * NPIX_ + nc);
            *p0 = make_float2(acc[mi][ni][0], acc[mi][ni][1]);
            *p1 = make_float2(acc[mi][ni][2], acc[mi][ni][3]);
        }
    }
}

// ---------------------------------------------------------------------------
extern "C" void kernel_launch(void* const* d_in, const int* in_sizes, int n_in,
                              void* d_out, int out_size) {
    const float* x = (const float*)d_in[0];   // [32,256,64,64]
    const float* w = (const float*)d_in[1];   // [256,256,3,3]
    float* out = (float*)d_out;               // [32,256,32,32]

    cudaFuncSetAttribute(conv_fp16_kernel,
                         cudaFuncAttributeMaxDynamicSharedMemorySize, SMEM_TOTAL);

    transform_kernel<<<2304 + 32768, 256>>>(x, w);
    {
        dim3 grid(COUT_ / BM, (B_ * NPIX_) / BN);   // (2, 128)
        conv_fp16_kernel<<<grid, 512, SMEM_TOTAL>>>(out);
    }
}

// round 10
// speedup vs baseline: 1.2421x; 1.2421x over previous
#include <cuda_runtime.h>
#include <cuda_fp16.h>
#include <cstdint>

// ---------------------------------------------------------------------------
// B=32, CIN=256, COUT=256, 64x64 -> 32x32, 3x3 stride2 pad1 conv. Crop mask
// all-True => plain conv. fp16 m16n8k16 two-term split GEMM:
//   C = Ahi*Bhi + Alo*Bhi   (weights split hi/lo fp16, x single fp16)
// Round 10: BN=128, 256 threads, 2 CTAs resident per SM (cross-CTA bubble
// overlap); R8-style syncthreads pipeline (mbarrier fabric reverted).
// ---------------------------------------------------------------------------

#define B_    32
#define CIN_  256
#define COUT_ 256
#define H_    64
#define W_    64
#define HW_   4096
#define NPIX_ 1024

#define BM 128
#define BN 128
#define KC 64
#define NIT 36                 // 9 taps * 4 cin-chunks

#define ROW_B    144
#define AH_OFF   0
#define AL_OFF   (128 * ROW_B)             // 18432
#define B_OFF2   (2 * 128 * ROW_B)         // 36864
#define STAGE_B  (B_OFF2 + 128 * ROW_B)    // 55296
#define TILES_OFF 1024
#define NSTAGE   2
#define SMEM_TOTAL (TILES_OFF + NSTAGE * STAGE_B)   // 111616 (x2 CTAs = 223232)

__device__ __align__(128) __half g_Ah[9 * COUT_ * CIN_];        // [p][cout][cin]
__device__ __align__(128) __half g_Al[9 * COUT_ * CIN_];
__device__ __align__(128) __half g_X[(size_t)B_ * HW_ * CIN_];  // [b][s][cin]

// ---------------------------------------------------------------------------
__device__ __forceinline__ uint32_t smem_u32(const void* p) {
    uint32_t a;
    asm("{ .reg .u64 t; cvta.to.shared.u64 t, %1; cvt.u32.u64 %0, t; }" : "=r"(a) : "l"(p));
    return a;
}
__device__ __forceinline__ void bulk_g2s(uint32_t dst, const void* src, uint32_t bytes,
                                         uint32_t mbar) {
    asm volatile(
        "cp.async.bulk.shared::cluster.global.mbarrier::complete_tx::bytes "
        "[%0], [%1], %2, [%3];"
        :: "r"(dst), "l"(src), "r"(bytes), "r"(mbar) : "memory");
}
__device__ __forceinline__ void mbar_init(uint32_t a, uint32_t cnt) {
    asm volatile("mbarrier.init.shared.b64 [%0], %1;" :: "r"(a), "r"(cnt) : "memory");
}
__device__ __forceinline__ void mbar_expect_tx(uint32_t a, uint32_t tx) {
    asm volatile("mbarrier.arrive.expect_tx.shared.b64 _, [%0], %1;"
                 :: "r"(a), "r"(tx) : "memory");
}
__device__ __forceinline__ void mbar_wait(uint32_t a, uint32_t parity) {
    asm volatile(
        "{\n\t.reg .pred P1;\n\t"
        "W_%=:\n\t"
        "mbarrier.try_wait.parity.acquire.cta.shared::cta.b64 P1, [%0], %1, 0x989680;\n\t"
        "@!P1 bra W_%=;\n\t}"
        :: "r"(a), "r"(parity) : "memory");
}
__device__ __forceinline__ void mma_fp16(float* d, const uint32_t* a, uint32_t b0, uint32_t b1) {
    asm volatile(
        "mma.sync.aligned.m16n8k16.row.col.f32.f16.f16.f32 "
        "{%0,%1,%2,%3}, {%4,%5,%6,%7}, {%8,%9}, {%0,%1,%2,%3};"
        : "+f"(d[0]), "+f"(d[1]), "+f"(d[2]), "+f"(d[3])
        : "r"(a[0]), "r"(a[1]), "r"(a[2]), "r"(a[3]), "r"(b0), "r"(b1));
}
__device__ __forceinline__ void ldm4(uint32_t* r, uint32_t addr) {
    asm volatile("ldmatrix.sync.aligned.m8n8.x4.shared.b16 {%0,%1,%2,%3}, [%4];"
                 : "=r"(r[0]), "=r"(r[1]), "=r"(r[2]), "=r"(r[3]) : "r"(addr));
}

// ---------------------------------------------------------------------------
// Fused prologue: blocks [0, 2304) -> weight split; [2304, 35072) -> x convert
// ---------------------------------------------------------------------------
__global__ void transform_kernel(const float* __restrict__ x, const float* __restrict__ w) {
    __shared__ float tile[32][33];   // tile[c_local][s_local]
    const int tid = threadIdx.x;
    if (blockIdx.x < 2304) {
        int idx = blockIdx.x * 256 + tid;           // over [p][cout][cin]
        int cin = idx & 255;
        int cout = (idx >> 8) & 255;
        int p = idx >> 16;
        float v = w[cout * (CIN_ * 9) + cin * 9 + p];
        __half hi = __float2half_rn(v);
        g_Ah[idx] = hi;
        g_Al[idx] = __float2half_rn(v - __half2float(hi));
        return;
    }
    const int t = blockIdx.x - 2304;
    const int s0 = (t & 127) * 32;
    const int c0 = ((t >> 7) & 7) * 32;
    const int b = t >> 10;
    const int tx = tid & 31, ty = tid >> 5;         // 32 x 8
    const float* xb = x + ((size_t)b * CIN_ + c0) * HW_ + s0;
#pragma unroll
    for (int k = 0; k < 4; ++k)
        tile[ty + 8 * k][tx] = xb[(size_t)(ty + 8 * k) * HW_ + tx];   // tile[c][s]
    __syncthreads();
    const int c2 = (tid & 15) * 2;
#pragma unroll
    for (int k = 0; k < 2; ++k) {
        const int s = (tid >> 4) + 16 * k;
        __half2 v = __floats2half2_rn(tile[c2][s], tile[c2 + 1][s]);
        size_t o = ((size_t)b * HW_ + s0 + s) * CIN_ + c0 + c2;
        *(__half2*)(g_X + o) = v;
    }
}

// ---------------------------------------------------------------------------
// Main fp16 implicit-GEMM. grid (2, 256), 256 threads (8 warps), 2 CTAs/SM.
// Warp tile 32x64: mw = (warp>>1)*32, nw = (warp&1)*64.
// ---------------------------------------------------------------------------
__global__ void __launch_bounds__(256, 2) conv_fp16_kernel(float* __restrict__ out) {
    extern __shared__ char smem[];
    const uint32_t sb = smem_u32(smem);
    const int tid = threadIdx.x;
    const int lane = tid & 31, warp = tid >> 5;
    const int m0 = blockIdx.x * BM;
    const int n0 = blockIdx.y * BN;
    const int b = n0 >> 10;
    const int pix0 = n0 & (NPIX_ - 1);

    if (tid < NSTAGE) mbar_init(sb + tid * 16, 1);
    asm volatile("fence.proxy.async.shared::cta;" ::: "memory");
    __syncthreads();

    // B loader: threads 0..127 own pixel pix0 + tid
    const int pixL = pix0 + (tid & 127);
    const int ohL = pixL >> 5, owL = pixL & 31;
    const __half* gX0 = g_X + (size_t)b * HW_ * CIN_;

    auto load_stage = [&](int buf, int s) {
        const int p = s >> 2;
        const int cin0 = (s & 3) * KC;
        const int kh = p / 3, kw = p - kh * 3;
        const uint32_t st = sb + TILES_OFF + buf * STAGE_B;
        const uint32_t mb = sb + buf * 16;
        if (tid == 0) {
            int invalid = (kw == 0 ? 4 : 0)
                        + ((kh == 0 && pix0 == 0) ? 32 : 0)
                        - ((kw == 0 && kh == 0 && pix0 == 0) ? 1 : 0);
            uint32_t tx = 32768u + 128u * (uint32_t)(128 - invalid);
            mbar_expect_tx(mb, tx);
        }
        // A rows: 256 threads cover hi (tid<128) and lo (tid>=128) planes
        const int ar = tid & 127;
        const __half* srcA = ((tid < 128) ? g_Ah : g_Al)
                           + (size_t)p * (COUT_ * CIN_) + (size_t)(m0 + ar) * CIN_ + cin0;
        bulk_g2s(st + ((tid < 128) ? AH_OFF : AL_OFF) + ar * ROW_B, srcA, 128, mb);
        // B rows: threads 0..127
        if (tid < 128) {
            const int ih = ohL * 2 - 1 + kh;
            const int iw = owL * 2 - 1 + kw;
            const uint32_t dst = st + B_OFF2 + tid * ROW_B;
            if (((unsigned)ih < (unsigned)H_) && ((unsigned)iw < (unsigned)W_)) {
                bulk_g2s(dst, gX0 + (size_t)(ih * W_ + iw) * CIN_ + cin0, 128, mb);
            } else {
#pragma unroll
                for (int j = 0; j < 8; ++j)
                    asm volatile("st.shared.v4.b32 [%0], {%1, %1, %1, %1};"
                                 :: "r"(dst + j * 16), "r"(0u) : "memory");
            }
        }
    };

    float acc[2][8][4];
#pragma unroll
    for (int mi = 0; mi < 2; ++mi)
#pragma unroll
        for (int ni = 0; ni < 8; ++ni)
#pragma unroll
            for (int j = 0; j < 4; ++j) acc[mi][ni][j] = 0.0f;

    load_stage(0, 0);
    load_stage(1, 1);
    __syncthreads();   // zero-STS of initial stages visible

    const int mw = (warp >> 1) * 32;      // 0,32,64,96
    const int nw = (warp & 1) * 64;       // 0,64
    uint32_t aOff[2], bOff[4];
#pragma unroll
    for (int mi = 0; mi < 2; ++mi)
        aOff[mi] = (uint32_t)((mw + mi * 16 + (lane & 15)) * ROW_B + (lane >> 4) * 16);
#pragma unroll
    for (int nj = 0; nj < 4; ++nj)
        bOff[nj] = (uint32_t)(B_OFF2
                 + (nw + nj * 16 + (lane & 7) + (lane >> 4) * 8) * ROW_B
                 + ((lane >> 3) & 1) * 16);

    int ph[NSTAGE] = {0, 0};

#pragma unroll 1
    for (int it = 0; it < NIT; ++it) {
        const int ib = it & 1;
        mbar_wait(sb + ib * 16, ph[ib]);
        ph[ib] ^= 1;
        const uint32_t st = sb + TILES_OFF + ib * STAGE_B;
#pragma unroll
        for (int ks = 0; ks < 4; ++ks) {
            const uint32_t kb = (uint32_t)(ks * 32);
            uint32_t ah[2][4], al[2][4], bf[4][4];
#pragma unroll
            for (int mi = 0; mi < 2; ++mi) {
                ldm4(ah[mi], st + aOff[mi] + kb);
                ldm4(al[mi], st + AL_OFF + aOff[mi] + kb);
            }
#pragma unroll
            for (int nj = 0; nj < 4; ++nj)
                ldm4(bf[nj], st + bOff[nj] + kb);
#pragma unroll
            for (int nj = 0; nj < 4; ++nj)
#pragma unroll
                for (int s2 = 0; s2 < 2; ++s2) {
                    const int ni = nj * 2 + s2;
                    const uint32_t b0 = bf[nj][s2 * 2];
                    const uint32_t b1 = bf[nj][s2 * 2 + 1];
#pragma unroll
                    for (int mi = 0; mi < 2; ++mi) {
                        mma_fp16(acc[mi][ni], ah[mi], b0, b1);
                        mma_fp16(acc[mi][ni], al[mi], b0, b1);
                    }
                }
        }
        __syncthreads();                      // stage drained by all warps
        if (it + NSTAGE < NIT) load_stage(ib, it + NSTAGE);
    }

    // ---- epilogue ----
    const int lg = lane >> 2;
    const int lc = lane & 3;
    float* ob = out + (size_t)b * COUT_ * NPIX_;
#pragma unroll
    for (int mi = 0; mi < 2; ++mi) {
        const int cout0 = m0 + mw + mi * 16 + lg;
#pragma unroll
        for (int ni = 0; ni < 8; ++ni) {
            const int nc = pix0 + nw + ni * 8 + lc * 2;
            float2* p0 = (float2*)(ob + (size_t)cout0 * NPIX_ + nc);
            float2* p1 = (float2*)(ob + (size_t)(cout0 + 8) * NPIX_ + nc);
            *p0 = make_float2(acc[mi][ni][0], acc[mi][ni][1]);
            *p1 = make_float2(acc[mi][ni][2], acc[mi][ni][3]);
        }
    }
}

// ---------------------------------------------------------------------------
extern "C" void kernel_launch(void* const* d_in, const int* in_sizes, int n_in,
                              void* d_out, int out_size) {
    const float* x = (const float*)d_in[0];   // [32,256,64,64]
    const float* w = (const float*)d_in[1];   // [256,256,3,3]
    float* out = (float*)d_out;               // [32,256,32,32]

    cudaFuncSetAttribute(conv_fp16_kernel,
                         cudaFuncAttributeMaxDynamicSharedMemorySize, SMEM_TOTAL);

    transform_kernel<<<2304 + 32768, 256>>>(x, w);
    {
        dim3 grid(COUT_ / BM, (B_ * NPIX_) / BN);   // (2, 256)
        conv_fp16_kernel<<<grid, 256, SMEM_TOTAL>>>(out);
    }
}

// round 11
// speedup vs baseline: 1.7814x; 1.4342x over previous
#include <cuda_runtime.h>
#include <cuda_fp16.h>
#include <cstdint>

// ---------------------------------------------------------------------------
// B=32, CIN=256, COUT=256, 64x64 -> 32x32, 3x3 stride2 pad1 conv. Crop mask
// all-True => plain conv. Round 11: SINGLE-PASS fp16 m16n8k16 implicit GEMM
// (fp16 mantissa == tf32 mantissa; single-pass tf32 measured 2.94e-4).
// BM=128, BN=128, 256 thr, 3-stage bulk pipeline, 2 CTAs/SM.
// ---------------------------------------------------------------------------

#define B_    32
#define CIN_  256
#define COUT_ 256
#define H_    64
#define W_    64
#define HW_   4096
#define NPIX_ 1024

#define BM 128
#define BN 128
#define KC 64
#define NIT 36                 // 9 taps * 4 cin-chunks

#define ROW_B    144
#define A_OFF    0
#define B_OFF2   (128 * ROW_B)             // 18432
#define STAGE_B  (B_OFF2 + 128 * ROW_B)    // 36864
#define TILES_OFF 1024
#define NSTAGE   3
#define SMEM_TOTAL (TILES_OFF + NSTAGE * STAGE_B)   // 111616 (x2 CTAs fits)

__device__ __align__(128) __half g_A[9 * COUT_ * CIN_];         // [p][cout][cin]
__device__ __align__(128) __half g_X[(size_t)B_ * HW_ * CIN_];  // [b][s][cin]

// ---------------------------------------------------------------------------
__device__ __forceinline__ uint32_t smem_u32(const void* p) {
    uint32_t a;
    asm("{ .reg .u64 t; cvta.to.shared.u64 t, %1; cvt.u32.u64 %0, t; }" : "=r"(a) : "l"(p));
    return a;
}
__device__ __forceinline__ void bulk_g2s(uint32_t dst, const void* src, uint32_t bytes,
                                         uint32_t mbar) {
    asm volatile(
        "cp.async.bulk.shared::cluster.global.mbarrier::complete_tx::bytes "
        "[%0], [%1], %2, [%3];"
        :: "r"(dst), "l"(src), "r"(bytes), "r"(mbar) : "memory");
}
__device__ __forceinline__ void mbar_init(uint32_t a, uint32_t cnt) {
    asm volatile("mbarrier.init.shared.b64 [%0], %1;" :: "r"(a), "r"(cnt) : "memory");
}
__device__ __forceinline__ void mbar_expect_tx(uint32_t a, uint32_t tx) {
    asm volatile("mbarrier.arrive.expect_tx.shared.b64 _, [%0], %1;"
                 :: "r"(a), "r"(tx) : "memory");
}
__device__ __forceinline__ void mbar_wait(uint32_t a, uint32_t parity) {
    asm volatile(
        "{\n\t.reg .pred P1;\n\t"
        "W_%=:\n\t"
        "mbarrier.try_wait.parity.acquire.cta.shared::cta.b64 P1, [%0], %1, 0x989680;\n\t"
        "@!P1 bra W_%=;\n\t}"
        :: "r"(a), "r"(parity) : "memory");
}
__device__ __forceinline__ void mma_fp16(float* d, const uint32_t* a, uint32_t b0, uint32_t b1) {
    asm volatile(
        "mma.sync.aligned.m16n8k16.row.col.f32.f16.f16.f32 "
        "{%0,%1,%2,%3}, {%4,%5,%6,%7}, {%8,%9}, {%0,%1,%2,%3};"
        : "+f"(d[0]), "+f"(d[1]), "+f"(d[2]), "+f"(d[3])
        : "r"(a[0]), "r"(a[1]), "r"(a[2]), "r"(a[3]), "r"(b0), "r"(b1));
}
__device__ __forceinline__ void ldm4(uint32_t* r, uint32_t addr) {
    asm volatile("ldmatrix.sync.aligned.m8n8.x4.shared.b16 {%0,%1,%2,%3}, [%4];"
                 : "=r"(r[0]), "=r"(r[1]), "=r"(r[2]), "=r"(r[3]) : "r"(addr));
}

// ---------------------------------------------------------------------------
// Fused prologue: blocks [0, 2304) -> weight convert; rest -> x convert
// ---------------------------------------------------------------------------
__global__ void transform_kernel(const float* __restrict__ x, const float* __restrict__ w) {
    __shared__ float tile[32][33];   // tile[c_local][s_local]
    const int tid = threadIdx.x;
    if (blockIdx.x < 2304) {
        int idx = blockIdx.x * 256 + tid;           // over [p][cout][cin]
        int cin = idx & 255;
        int cout = (idx >> 8) & 255;
        int p = idx >> 16;
        g_A[idx] = __float2half_rn(w[cout * (CIN_ * 9) + cin * 9 + p]);
        return;
    }
    const int t = blockIdx.x - 2304;
    const int s0 = (t & 127) * 32;
    const int c0 = ((t >> 7) & 7) * 32;
    const int b = t >> 10;
    const int tx = tid & 31, ty = tid >> 5;         // 32 x 8
    const float* xb = x + ((size_t)b * CIN_ + c0) * HW_ + s0;
#pragma unroll
    for (int k = 0; k < 4; ++k)
        tile[ty + 8 * k][tx] = xb[(size_t)(ty + 8 * k) * HW_ + tx];   // tile[c][s]
    __syncthreads();
    const int c2 = (tid & 15) * 2;
#pragma unroll
    for (int k = 0; k < 2; ++k) {
        const int s = (tid >> 4) + 16 * k;
        __half2 v = __floats2half2_rn(tile[c2][s], tile[c2 + 1][s]);
        size_t o = ((size_t)b * HW_ + s0 + s) * CIN_ + c0 + c2;
        *(__half2*)(g_X + o) = v;
    }
}

// ---------------------------------------------------------------------------
// Main fp16 implicit-GEMM. grid (2, 256), 256 threads (8 warps), 2 CTAs/SM.
// Warp tile 32x64: mw = (warp>>1)*32, nw = (warp&1)*64.
// ---------------------------------------------------------------------------
__global__ void __launch_bounds__(256, 2) conv_fp16_kernel(float* __restrict__ out) {
    extern __shared__ char smem[];
    const uint32_t sb = smem_u32(smem);
    const int tid = threadIdx.x;
    const int lane = tid & 31, warp = tid >> 5;
    const int m0 = blockIdx.x * BM;
    const int n0 = blockIdx.y * BN;
    const int b = n0 >> 10;
    const int pix0 = n0 & (NPIX_ - 1);

    if (tid < NSTAGE) mbar_init(sb + tid * 16, 1);
    asm volatile("fence.proxy.async.shared::cta;" ::: "memory");
    __syncthreads();

    // B loader: threads 128..255 own pixel pix0 + (tid-128)
    const int pixL = pix0 + (tid & 127);
    const int ohL = pixL >> 5, owL = pixL & 31;
    const __half* gX0 = g_X + (size_t)b * HW_ * CIN_;

    auto load_stage = [&](int buf, int s) {
        const int p = s >> 2;
        const int cin0 = (s & 3) * KC;
        const int kh = p / 3, kw = p - kh * 3;
        const uint32_t st = sb + TILES_OFF + buf * STAGE_B;
        const uint32_t mb = sb + buf * 16;
        if (tid == 0) {
            int invalid = (kw == 0 ? 4 : 0)
                        + ((kh == 0 && pix0 == 0) ? 32 : 0)
                        - ((kw == 0 && kh == 0 && pix0 == 0) ? 1 : 0);
            uint32_t tx = 16384u + 128u * (uint32_t)(128 - invalid);
            mbar_expect_tx(mb, tx);
        }
        const int r = tid & 127;
        if (tid < 128) {
            // A row r
            const __half* srcA = g_A + (size_t)p * (COUT_ * CIN_)
                               + (size_t)(m0 + r) * CIN_ + cin0;
            bulk_g2s(st + A_OFF + r * ROW_B, srcA, 128, mb);
        } else {
            // B row r (pixel pix0 + r)
            const int ih = ohL * 2 - 1 + kh;
            const int iw = owL * 2 - 1 + kw;
            const uint32_t dst = st + B_OFF2 + r * ROW_B;
            if (((unsigned)ih < (unsigned)H_) && ((unsigned)iw < (unsigned)W_)) {
                bulk_g2s(dst, gX0 + (size_t)(ih * W_ + iw) * CIN_ + cin0, 128, mb);
            } else {
#pragma unroll
                for (int j = 0; j < 8; ++j)
                    asm volatile("st.shared.v4.b32 [%0], {%1, %1, %1, %1};"
                                 :: "r"(dst + j * 16), "r"(0u) : "memory");
            }
        }
    };

    float acc[2][8][4];
#pragma unroll
    for (int mi = 0; mi < 2; ++mi)
#pragma unroll
        for (int ni = 0; ni < 8; ++ni)
#pragma unroll
            for (int j = 0; j < 4; ++j) acc[mi][ni][j] = 0.0f;

    load_stage(0, 0);
    load_stage(1, 1);
    load_stage(2, 2);
    __syncthreads();   // zero-STS of initial stages visible

    const int mw = (warp >> 1) * 32;      // 0,32,64,96
    const int nw = (warp & 1) * 64;       // 0,64
    uint32_t aOff[2], bOff[4];
#pragma unroll
    for (int mi = 0; mi < 2; ++mi)
        aOff[mi] = (uint32_t)(A_OFF + (mw + mi * 16 + (lane & 15)) * ROW_B
                   + (lane >> 4) * 16);
#pragma unroll
    for (int nj = 0; nj < 4; ++nj)
        bOff[nj] = (uint32_t)(B_OFF2
                 + (nw + nj * 16 + (lane & 7) + (lane >> 4) * 8) * ROW_B
                 + ((lane >> 3) & 1) * 16);

    int ph[NSTAGE] = {0, 0, 0};
    int ib = 0;

#pragma unroll 1
    for (int it = 0; it < NIT; ++it) {
        mbar_wait(sb + ib * 16, ph[ib]);
        ph[ib] ^= 1;
        const uint32_t st = sb + TILES_OFF + ib * STAGE_B;
#pragma unroll
        for (int ks = 0; ks < 4; ++ks) {
            const uint32_t kb = (uint32_t)(ks * 32);
            uint32_t a[2][4], bf[4][4];
#pragma unroll
            for (int mi = 0; mi < 2; ++mi)
                ldm4(a[mi], st + aOff[mi] + kb);
#pragma unroll
            for (int nj = 0; nj < 4; ++nj)
                ldm4(bf[nj], st + bOff[nj] + kb);
#pragma unroll
            for (int nj = 0; nj < 4; ++nj)
#pragma unroll
                for (int s2 = 0; s2 < 2; ++s2) {
                    const int ni = nj * 2 + s2;
                    const uint32_t b0 = bf[nj][s2 * 2];
                    const uint32_t b1 = bf[nj][s2 * 2 + 1];
#pragma unroll
                    for (int mi = 0; mi < 2; ++mi)
                        mma_fp16(acc[mi][ni], a[mi], b0, b1);
                }
        }
        __syncthreads();                      // stage drained by all warps
        if (it + NSTAGE < NIT) load_stage(ib, it + NSTAGE);
        if (++ib == NSTAGE) ib = 0;
    }

    // ---- epilogue ----
    const int lg = lane >> 2;
    const int lc = lane & 3;
    float* ob = out + (size_t)b * COUT_ * NPIX_;
#pragma unroll
    for (int mi = 0; mi < 2; ++mi) {
        const int cout0 = m0 + mw + mi * 16 + lg;
#pragma unroll
        for (int ni = 0; ni < 8; ++ni) {
            const int nc = pix0 + nw + ni * 8 + lc * 2;
            float2* p0 = (float2*)(ob + (size_t)cout0 * NPIX_ + nc);
            float2* p1 = (float2*)(ob + (size_t)(cout0 + 8) * NPIX_ + nc);
            *p0 = make_float2(acc[mi][ni][0], acc[mi][ni][1]);
            *p1 = make_float2(acc[mi][ni][2], acc[mi][ni][3]);
        }
    }
}

// ---------------------------------------------------------------------------
extern "C" void kernel_launch(void* const* d_in, const int* in_sizes, int n_in,
                              void* d_out, int out_size) {
    const float* x = (const float*)d_in[0];   // [32,256,64,64]
    const float* w = (const float*)d_in[1];   // [256,256,3,3]
    float* out = (float*)d_out;               // [32,256,32,32]

    cudaFuncSetAttribute(conv_fp16_kernel,
                         cudaFuncAttributeMaxDynamicSharedMemorySize, SMEM_TOTAL);

    transform_kernel<<<2304 + 32768, 256>>>(x, w);
    {
        dim3 grid(COUT_ / BM, (B_ * NPIX_) / BN);   // (2, 256)
        conv_fp16_kernel<<<grid, 256, SMEM_TOTAL>>>(out);
    }
}

// round 12
// speedup vs baseline: 1.9724x; 1.1072x over previous
#include <cuda_runtime.h>
#include <cuda_fp16.h>
#include <cstdint>

// ---------------------------------------------------------------------------
// B=32, CIN=256, COUT=256, 64x64 -> 32x32, 3x3 stride2 pad1 conv. Crop mask
// all-True => plain conv. Single-pass fp16 m16n8k16 implicit GEMM.
// Round 12: KC=96 (24 iters, amortize per-iter barrier tax), 2-stage
// pipeline, 2 CTAs/SM. A relaid [cout][k'] contiguous; B chunks may span a
// tap boundary -> up to 2 bulk segments per row.
// ---------------------------------------------------------------------------

#define B_    32
#define CIN_  256
#define COUT_ 256
#define H_    64
#define W_    64
#define HW_   4096
#define NPIX_ 1024
#define KTOT  2304

#define BM 128
#define BN 128
#define KC 96
#define NIT 24                 // 2304 / 96

#define ROW_B    208           // 192B payload + 16B pad (13r mod 32 distinct)
#define A_OFF    0
#define B_OFF2   (128 * ROW_B)             // 26624
#define STAGE_B  (B_OFF2 + 128 * ROW_B)    // 53248
#define TILES_OFF 1024
#define NSTAGE   2
#define SMEM_TOTAL (TILES_OFF + NSTAGE * STAGE_B)   // 107520 (x2 CTAs = 215040)

__device__ __align__(128) __half g_A[COUT_ * KTOT];             // [cout][p*256+cin]
__device__ __align__(128) __half g_X[(size_t)B_ * HW_ * CIN_];  // [b][s][cin]

// ---------------------------------------------------------------------------
__device__ __forceinline__ uint32_t smem_u32(const void* p) {
    uint32_t a;
    asm("{ .reg .u64 t; cvta.to.shared.u64 t, %1; cvt.u32.u64 %0, t; }" : "=r"(a) : "l"(p));
    return a;
}
__device__ __forceinline__ void bulk_g2s(uint32_t dst, const void* src, uint32_t bytes,
                                         uint32_t mbar) {
    asm volatile(
        "cp.async.bulk.shared::cluster.global.mbarrier::complete_tx::bytes "
        "[%0], [%1], %2, [%3];"
        :: "r"(dst), "l"(src), "r"(bytes), "r"(mbar) : "memory");
}
__device__ __forceinline__ void mbar_init(uint32_t a, uint32_t cnt) {
    asm volatile("mbarrier.init.shared.b64 [%0], %1;" :: "r"(a), "r"(cnt) : "memory");
}
__device__ __forceinline__ void mbar_expect_tx(uint32_t a, uint32_t tx) {
    asm volatile("mbarrier.arrive.expect_tx.shared.b64 _, [%0], %1;"
                 :: "r"(a), "r"(tx) : "memory");
}
__device__ __forceinline__ void mbar_wait(uint32_t a, uint32_t parity) {
    asm volatile(
        "{\n\t.reg .pred P1;\n\t"
        "W_%=:\n\t"
        "mbarrier.try_wait.parity.acquire.cta.shared::cta.b64 P1, [%0], %1, 0x989680;\n\t"
        "@!P1 bra W_%=;\n\t}"
        :: "r"(a), "r"(parity) : "memory");
}
__device__ __forceinline__ void mma_fp16(float* d, const uint32_t* a, uint32_t b0, uint32_t b1) {
    asm volatile(
        "mma.sync.aligned.m16n8k16.row.col.f32.f16.f16.f32 "
        "{%0,%1,%2,%3}, {%4,%5,%6,%7}, {%8,%9}, {%0,%1,%2,%3};"
        : "+f"(d[0]), "+f"(d[1]), "+f"(d[2]), "+f"(d[3])
        : "r"(a[0]), "r"(a[1]), "r"(a[2]), "r"(a[3]), "r"(b0), "r"(b1));
}
__device__ __forceinline__ void ldm4(uint32_t* r, uint32_t addr) {
    asm volatile("ldmatrix.sync.aligned.m8n8.x4.shared.b16 {%0,%1,%2,%3}, [%4];"
                 : "=r"(r[0]), "=r"(r[1]), "=r"(r[2]), "=r"(r[3]) : "r"(addr));
}

// ---------------------------------------------------------------------------
// Fused prologue: blocks [0, 2304) -> weight convert; rest -> x convert
// ---------------------------------------------------------------------------
__global__ void transform_kernel(const float* __restrict__ x, const float* __restrict__ w) {
    __shared__ float tile[32][33];   // tile[c_local][s_local]
    const int tid = threadIdx.x;
    if (blockIdx.x < 2304) {
        int idx = blockIdx.x * 256 + tid;   // linear over [cout][p][cin]
        int cin = idx & 255;
        int p = (idx >> 8) % 9;
        int cout = idx / KTOT;
        g_A[idx] = __float2half_rn(w[cout * KTOT + cin * 9 + p]);
        return;
    }
    const int t = blockIdx.x - 2304;
    const int s0 = (t & 127) * 32;
    const int c0 = ((t >> 7) & 7) * 32;
    const int b = t >> 10;
    const int tx = tid & 31, ty = tid >> 5;         // 32 x 8
    const float* xb = x + ((size_t)b * CIN_ + c0) * HW_ + s0;
#pragma unroll
    for (int k = 0; k < 4; ++k)
        tile[ty + 8 * k][tx] = xb[(size_t)(ty + 8 * k) * HW_ + tx];   // tile[c][s]
    __syncthreads();
    const int c2 = (tid & 15) * 2;
#pragma unroll
    for (int k = 0; k < 2; ++k) {
        const int s = (tid >> 4) + 16 * k;
        __half2 v = __floats2half2_rn(tile[c2][s], tile[c2 + 1][s]);
        size_t o = ((size_t)b * HW_ + s0 + s) * CIN_ + c0 + c2;
        *(__half2*)(g_X + o) = v;
    }
}

// ---------------------------------------------------------------------------
// Main fp16 implicit-GEMM. grid (2, 256), 256 threads (8 warps), 2 CTAs/SM.
// ---------------------------------------------------------------------------
__global__ void __launch_bounds__(256, 2) conv_fp16_kernel(float* __restrict__ out) {
    extern __shared__ char smem[];
    const uint32_t sb = smem_u32(smem);
    const int tid = threadIdx.x;
    const int lane = tid & 31, warp = tid >> 5;
    const int m0 = blockIdx.x * BM;
    const int n0 = blockIdx.y * BN;
    const int b = n0 >> 10;
    const int pix0 = n0 & (NPIX_ - 1);

    if (tid < NSTAGE) mbar_init(sb + tid * 16, 1);
    asm volatile("fence.proxy.async.shared::cta;" ::: "memory");
    __syncthreads();

    const int pixL = pix0 + (tid & 127);
    const int ohL = pixL >> 5, owL = pixL & 31;
    const __half* gX0 = g_X + (size_t)b * HW_ * CIN_;

    // invalid-row count for tap p within this BN=128 pixel block
    auto inv_rows = [&](int p) -> int {
        const int kh = p / 3, kw = p - (p / 3) * 3;
        int inv = (kw == 0 ? 4 : 0) + ((kh == 0 && pix0 == 0) ? 32 : 0);
        if (kw == 0 && kh == 0 && pix0 == 0) inv -= 1;
        return inv;
    };

    auto load_stage = [&](int buf, int it) {
        const int k0 = it * KC;
        const int p1 = k0 >> 8;
        const int o1 = k0 & 255;
        const int len1 = (256 - o1 < KC) ? (256 - o1) : KC;   // elements
        const int len2 = KC - len1;                            // 0 if no split
        const uint32_t st = sb + TILES_OFF + buf * STAGE_B;
        const uint32_t mb = sb + buf * 16;
        if (tid == 0) {
            uint32_t txB = 2u * (uint32_t)len1 * (uint32_t)(128 - inv_rows(p1));
            if (len2) txB += 2u * (uint32_t)len2 * (uint32_t)(128 - inv_rows(p1 + 1));
            mbar_expect_tx(mb, 128u * 192u + txB);
        }
        const int r = tid & 127;
        if (tid < 128) {
            // A row r: contiguous in [cout][k']
            bulk_g2s(st + A_OFF + r * ROW_B,
                     g_A + (size_t)(m0 + r) * KTOT + k0, KC * 2, mb);
        } else {
            const uint32_t dst = st + B_OFF2 + r * ROW_B;
            // segment 1: tap p1, cin [o1, o1+len1)
            {
                const int kh = p1 / 3, kw = p1 - (p1 / 3) * 3;
                const int ih = ohL * 2 - 1 + kh;
                const int iw = owL * 2 - 1 + kw;
                if (((unsigned)ih < (unsigned)H_) && ((unsigned)iw < (unsigned)W_)) {
                    bulk_g2s(dst, gX0 + (size_t)(ih * W_ + iw) * CIN_ + o1, len1 * 2, mb);
                } else {
                    for (int j = 0; j < len1 * 2; j += 16)
                        asm volatile("st.shared.v4.b32 [%0], {%1, %1, %1, %1};"
                                     :: "r"(dst + j), "r"(0u) : "memory");
                }
            }
            // segment 2: tap p1+1, cin [0, len2)
            if (len2) {
                const int p2 = p1 + 1;
                const int kh = p2 / 3, kw = p2 - (p2 / 3) * 3;
                const int ih = ohL * 2 - 1 + kh;
                const int iw = owL * 2 - 1 + kw;
                const uint32_t d2 = dst + len1 * 2;
                if (((unsigned)ih < (unsigned)H_) && ((unsigned)iw < (unsigned)W_)) {
                    bulk_g2s(d2, gX0 + (size_t)(ih * W_ + iw) * CIN_, len2 * 2, mb);
                } else {
                    for (int j = 0; j < len2 * 2; j += 16)
                        asm volatile("st.shared.v4.b32 [%0], {%1, %1, %1, %1};"
                                     :: "r"(d2 + j), "r"(0u) : "memory");
                }
            }
        }
    };

    float acc[2][8][4];
#pragma unroll
    for (int mi = 0; mi < 2; ++mi)
#pragma unroll
        for (int ni = 0; ni < 8; ++ni)
#pragma unroll
            for (int j = 0; j < 4; ++j) acc[mi][ni][j] = 0.0f;

    load_stage(0, 0);
    load_stage(1, 1);
    __syncthreads();   // zero-STS of initial stages visible

    const int mw = (warp >> 1) * 32;      // 0,32,64,96
    const int nw = (warp & 1) * 64;       // 0,64
    uint32_t aOff[2], bOff[4];
#pragma unroll
    for (int mi = 0; mi < 2; ++mi)
        aOff[mi] = (uint32_t)(A_OFF + (mw + mi * 16 + (lane & 15)) * ROW_B
                   + (lane >> 4) * 16);
#pragma unroll
    for (int nj = 0; nj < 4; ++nj)
        bOff[nj] = (uint32_t)(B_OFF2
                 + (nw + nj * 16 + (lane & 7) + (lane >> 4) * 8) * ROW_B
                 + ((lane >> 3) & 1) * 16);

    int ph[NSTAGE] = {0, 0};

#pragma unroll 1
    for (int it = 0; it < NIT; ++it) {
        const int ib = it & 1;
        mbar_wait(sb + ib * 16, ph[ib]);
        ph[ib] ^= 1;
        const uint32_t st = sb + TILES_OFF + ib * STAGE_B;
#pragma unroll
        for (int ks = 0; ks < 6; ++ks) {
            const uint32_t kb = (uint32_t)(ks * 32);
            uint32_t a[2][4], bf[4][4];
#pragma unroll
            for (int mi = 0; mi < 2; ++mi)
                ldm4(a[mi], st + aOff[mi] + kb);
#pragma unroll
            for (int nj = 0; nj < 4; ++nj)
                ldm4(bf[nj], st + bOff[nj] + kb);
#pragma unroll
            for (int nj = 0; nj < 4; ++nj)
#pragma unroll
                for (int s2 = 0; s2 < 2; ++s2) {
                    const int ni = nj * 2 + s2;
                    const uint32_t b0 = bf[nj][s2 * 2];
                    const uint32_t b1 = bf[nj][s2 * 2 + 1];
#pragma unroll
                    for (int mi = 0; mi < 2; ++mi)
                        mma_fp16(acc[mi][ni], a[mi], b0, b1);
                }
        }
        __syncthreads();                      // stage drained by all warps
        if (it + NSTAGE < NIT) load_stage(ib, it + NSTAGE);
    }

    // ---- epilogue ----
    const int lg = lane >> 2;
    const int lc = lane & 3;
    float* ob = out + (size_t)b * COUT_ * NPIX_;
#pragma unroll
    for (int mi = 0; mi < 2; ++mi) {
        const int cout0 = m0 + mw + mi * 16 + lg;
#pragma unroll
        for (int ni = 0; ni < 8; ++ni) {
            const int nc = pix0 + nw + ni * 8 + lc * 2;
            float2* p0 = (float2*)(ob + (size_t)cout0 * NPIX_ + nc);
            float2* p1 = (float2*)(ob + (size_t)(cout0 + 8) * NPIX_ + nc);
            *p0 = make_float2(acc[mi][ni][0], acc[mi][ni][1]);
            *p1 = make_float2(acc[mi][ni][2], acc[mi][ni][3]);
        }
    }
}

// ---------------------------------------------------------------------------
extern "C" void kernel_launch(void* const* d_in, const int* in_sizes, int n_in,
                              void* d_out, int out_size) {
    const float* x = (const float*)d_in[0];   // [32,256,64,64]
    const float* w = (const float*)d_in[1];   // [256,256,3,3]
    float* out = (float*)d_out;               // [32,256,32,32]

    cudaFuncSetAttribute(conv_fp16_kernel,
                         cudaFuncAttributeMaxDynamicSharedMemorySize, SMEM_TOTAL);

    transform_kernel<<<2304 + 32768, 256>>>(x, w);
    {
        dim3 grid(COUT_ / BM, (B_ * NPIX_) / BN);   // (2, 256)
        conv_fp16_kernel<<<grid, 256, SMEM_TOTAL>>>(out);
    }
}

// round 13
// speedup vs baseline: 2.0237x; 1.0260x over previous
#include <cuda_runtime.h>
#include <cuda_fp16.h>
#include <cstdint>

// ---------------------------------------------------------------------------
// B=32, CIN=256, COUT=256, 64x64 -> 32x32, 3x3 stride2 pad1 conv. Crop mask
// all-True => plain conv. Single-pass fp16 m16n8k16 implicit GEMM.
// Round 13: KC=96, 2-stage, 2 CTAs/SM, PAIRED iterations -> one
// __syncthreads + one reload per 2 chunks (halves per-iter barrier tax).
// ---------------------------------------------------------------------------

#define B_    32
#define CIN_  256
#define COUT_ 256
#define H_    64
#define W_    64
#define HW_   4096
#define NPIX_ 1024
#define KTOT  2304

#define BM 128
#define BN 128
#define KC 96
#define NIT 24                 // 2304 / 96

#define ROW_B    208           // 192B payload + 16B pad
#define A_OFF    0
#define B_OFF2   (128 * ROW_B)             // 26624
#define STAGE_B  (B_OFF2 + 128 * ROW_B)    // 53248
#define TILES_OFF 1024
#define NSTAGE   2
#define SMEM_TOTAL (TILES_OFF + NSTAGE * STAGE_B)   // 107520 (x2 CTAs = 215040)

__device__ __align__(128) __half g_A[COUT_ * KTOT];             // [cout][p*256+cin]
__device__ __align__(128) __half g_X[(size_t)B_ * HW_ * CIN_];  // [b][s][cin]

// ---------------------------------------------------------------------------
__device__ __forceinline__ uint32_t smem_u32(const void* p) {
    uint32_t a;
    asm("{ .reg .u64 t; cvta.to.shared.u64 t, %1; cvt.u32.u64 %0, t; }" : "=r"(a) : "l"(p));
    return a;
}
__device__ __forceinline__ void bulk_g2s(uint32_t dst, const void* src, uint32_t bytes,
                                         uint32_t mbar) {
    asm volatile(
        "cp.async.bulk.shared::cluster.global.mbarrier::complete_tx::bytes "
        "[%0], [%1], %2, [%3];"
        :: "r"(dst), "l"(src), "r"(bytes), "r"(mbar) : "memory");
}
__device__ __forceinline__ void mbar_init(uint32_t a, uint32_t cnt) {
    asm volatile("mbarrier.init.shared.b64 [%0], %1;" :: "r"(a), "r"(cnt) : "memory");
}
__device__ __forceinline__ void mbar_expect_tx(uint32_t a, uint32_t tx) {
    asm volatile("mbarrier.arrive.expect_tx.shared.b64 _, [%0], %1;"
                 :: "r"(a), "r"(tx) : "memory");
}
__device__ __forceinline__ void mbar_wait(uint32_t a, uint32_t parity) {
    asm volatile(
        "{\n\t.reg .pred P1;\n\t"
        "W_%=:\n\t"
        "mbarrier.try_wait.parity.acquire.cta.shared::cta.b64 P1, [%0], %1, 0x989680;\n\t"
        "@!P1 bra W_%=;\n\t}"
        :: "r"(a), "r"(parity) : "memory");
}
__device__ __forceinline__ void mma_fp16(float* d, const uint32_t* a, uint32_t b0, uint32_t b1) {
    asm volatile(
        "mma.sync.aligned.m16n8k16.row.col.f32.f16.f16.f32 "
        "{%0,%1,%2,%3}, {%4,%5,%6,%7}, {%8,%9}, {%0,%1,%2,%3};"
        : "+f"(d[0]), "+f"(d[1]), "+f"(d[2]), "+f"(d[3])
        : "r"(a[0]), "r"(a[1]), "r"(a[2]), "r"(a[3]), "r"(b0), "r"(b1));
}
__device__ __forceinline__ void ldm4(uint32_t* r, uint32_t addr) {
    asm volatile("ldmatrix.sync.aligned.m8n8.x4.shared.b16 {%0,%1,%2,%3}, [%4];"
                 : "=r"(r[0]), "=r"(r[1]), "=r"(r[2]), "=r"(r[3]) : "r"(addr));
}

// ---------------------------------------------------------------------------
// Fused prologue: blocks [0, 2304) -> weight convert; rest -> x convert
// ---------------------------------------------------------------------------
__global__ void transform_kernel(const float* __restrict__ x, const float* __restrict__ w) {
    __shared__ float tile[32][33];   // tile[c_local][s_local]
    const int tid = threadIdx.x;
    if (blockIdx.x < 2304) {
        int idx = blockIdx.x * 256 + tid;   // linear over [cout][p][cin]
        int cin = idx & 255;
        int p = (idx >> 8) % 9;
        int cout = idx / KTOT;
        g_A[idx] = __float2half_rn(w[cout * KTOT + cin * 9 + p]);
        return;
    }
    const int t = blockIdx.x - 2304;
    const int s0 = (t & 127) * 32;
    const int c0 = ((t >> 7) & 7) * 32;
    const int b = t >> 10;
    const int tx = tid & 31, ty = tid >> 5;         // 32 x 8
    const float* xb = x + ((size_t)b * CIN_ + c0) * HW_ + s0;
#pragma unroll
    for (int k = 0; k < 4; ++k)
        tile[ty + 8 * k][tx] = xb[(size_t)(ty + 8 * k) * HW_ + tx];   // tile[c][s]
    __syncthreads();
    const int c2 = (tid & 15) * 2;
#pragma unroll
    for (int k = 0; k < 2; ++k) {
        const int s = (tid >> 4) + 16 * k;
        __half2 v = __floats2half2_rn(tile[c2][s], tile[c2 + 1][s]);
        size_t o = ((size_t)b * HW_ + s0 + s) * CIN_ + c0 + c2;
        *(__half2*)(g_X + o) = v;
    }
}

// ---------------------------------------------------------------------------
// Main fp16 implicit-GEMM. grid (2, 256), 256 threads (8 warps), 2 CTAs/SM.
// ---------------------------------------------------------------------------
__global__ void __launch_bounds__(256, 2) conv_fp16_kernel(float* __restrict__ out) {
    extern __shared__ char smem[];
    const uint32_t sb = smem_u32(smem);
    const int tid = threadIdx.x;
    const int lane = tid & 31, warp = tid >> 5;
    const int m0 = blockIdx.x * BM;
    const int n0 = blockIdx.y * BN;
    const int b = n0 >> 10;
    const int pix0 = n0 & (NPIX_ - 1);

    if (tid < NSTAGE) mbar_init(sb + tid * 16, 1);
    asm volatile("fence.proxy.async.shared::cta;" ::: "memory");
    __syncthreads();

    const int pixL = pix0 + (tid & 127);
    const int ohL = pixL >> 5, owL = pixL & 31;
    const __half* gX0 = g_X + (size_t)b * HW_ * CIN_;

    auto inv_rows = [&](int p) -> int {
        const int kh = p / 3, kw = p - (p / 3) * 3;
        int inv = (kw == 0 ? 4 : 0) + ((kh == 0 && pix0 == 0) ? 32 : 0);
        if (kw == 0 && kh == 0 && pix0 == 0) inv -= 1;
        return inv;
    };

    auto load_stage = [&](int buf, int it) {
        const int k0 = it * KC;
        const int p1 = k0 >> 8;
        const int o1 = k0 & 255;
        const int len1 = (256 - o1 < KC) ? (256 - o1) : KC;   // elements
        const int len2 = KC - len1;                            // 0 if no split
        const uint32_t st = sb + TILES_OFF + buf * STAGE_B;
        const uint32_t mb = sb + buf * 16;
        if (tid == 0) {
            uint32_t txB = 2u * (uint32_t)len1 * (uint32_t)(128 - inv_rows(p1));
            if (len2) txB += 2u * (uint32_t)len2 * (uint32_t)(128 - inv_rows(p1 + 1));
            mbar_expect_tx(mb, 128u * 192u + txB);
        }
        const int r = tid & 127;
        if (tid < 128) {
            bulk_g2s(st + A_OFF + r * ROW_B,
                     g_A + (size_t)(m0 + r) * KTOT + k0, KC * 2, mb);
        } else {
            const uint32_t dst = st + B_OFF2 + r * ROW_B;
            {
                const int kh = p1 / 3, kw = p1 - (p1 / 3) * 3;
                const int ih = ohL * 2 - 1 + kh;
                const int iw = owL * 2 - 1 + kw;
                if (((unsigned)ih < (unsigned)H_) && ((unsigned)iw < (unsigned)W_)) {
                    bulk_g2s(dst, gX0 + (size_t)(ih * W_ + iw) * CIN_ + o1, len1 * 2, mb);
                } else {
                    for (int j = 0; j < len1 * 2; j += 16)
                        asm volatile("st.shared.v4.b32 [%0], {%1, %1, %1, %1};"
                                     :: "r"(dst + j), "r"(0u) : "memory");
                }
            }
            if (len2) {
                const int p2 = p1 + 1;
                const int kh = p2 / 3, kw = p2 - (p2 / 3) * 3;
                const int ih = ohL * 2 - 1 + kh;
                const int iw = owL * 2 - 1 + kw;
                const uint32_t d2 = dst + len1 * 2;
                if (((unsigned)ih < (unsigned)H_) && ((unsigned)iw < (unsigned)W_)) {
                    bulk_g2s(d2, gX0 + (size_t)(ih * W_ + iw) * CIN_, len2 * 2, mb);
                } else {
                    for (int j = 0; j < len2 * 2; j += 16)
                        asm volatile("st.shared.v4.b32 [%0], {%1, %1, %1, %1};"
                                     :: "r"(d2 + j), "r"(0u) : "memory");
                }
            }
        }
    };

    float acc[2][8][4];
#pragma unroll
    for (int mi = 0; mi < 2; ++mi)
#pragma unroll
        for (int ni = 0; ni < 8; ++ni)
#pragma unroll
            for (int j = 0; j < 4; ++j) acc[mi][ni][j] = 0.0f;

    load_stage(0, 0);
    load_stage(1, 1);
    __syncthreads();   // zero-STS of initial stages visible

    const int mw = (warp >> 1) * 32;      // 0,32,64,96
    const int nw = (warp & 1) * 64;       // 0,64
    uint32_t aOff[2], bOff[4];
#pragma unroll
    for (int mi = 0; mi < 2; ++mi)
        aOff[mi] = (uint32_t)(A_OFF + (mw + mi * 16 + (lane & 15)) * ROW_B
                   + (lane >> 4) * 16);
#pragma unroll
    for (int nj = 0; nj < 4; ++nj)
        bOff[nj] = (uint32_t)(B_OFF2
                 + (nw + nj * 16 + (lane & 7) + (lane >> 4) * 8) * ROW_B
                 + ((lane >> 3) & 1) * 16);

    int ph = 0;   // shared parity for both stages (each reloaded once/pair)

    auto compute_stage = [&](int buf) {
        const uint32_t st = sb + TILES_OFF + buf * STAGE_B;
#pragma unroll
        for (int ks = 0; ks < 6; ++ks) {
            const uint32_t kb = (uint32_t)(ks * 32);
            uint32_t a[2][4], bf[4][4];
#pragma unroll
            for (int mi = 0; mi < 2; ++mi)
                ldm4(a[mi], st + aOff[mi] + kb);
#pragma unroll
            for (int nj = 0; nj < 4; ++nj)
                ldm4(bf[nj], st + bOff[nj] + kb);
#pragma unroll
            for (int nj = 0; nj < 4; ++nj)
#pragma unroll
                for (int s2 = 0; s2 < 2; ++s2) {
                    const int ni = nj * 2 + s2;
                    const uint32_t b0 = bf[nj][s2 * 2];
                    const uint32_t b1 = bf[nj][s2 * 2 + 1];
#pragma unroll
                    for (int mi = 0; mi < 2; ++mi)
                        mma_fp16(acc[mi][ni], a[mi], b0, b1);
                }
        }
    };

#pragma unroll 1
    for (int jp = 0; jp < NIT / 2; ++jp) {
        mbar_wait(sb + 0 * 16, ph);
        compute_stage(0);
        mbar_wait(sb + 1 * 16, ph);
        compute_stage(1);
        ph ^= 1;
        __syncthreads();                      // both stages drained by all warps
        if (2 * jp + 2 < NIT) {
            load_stage(0, 2 * jp + 2);
            load_stage(1, 2 * jp + 3);
        }
    }

    // ---- epilogue ----
    const int lg = lane >> 2;
    const int lc = lane & 3;
    float* ob = out + (size_t)b * COUT_ * NPIX_;
#pragma unroll
    for (int mi = 0; mi < 2; ++mi) {
        const int cout0 = m0 + mw + mi * 16 + lg;
#pragma unroll
        for (int ni = 0; ni < 8; ++ni) {
            const int nc = pix0 + nw + ni * 8 + lc * 2;
            float2* p0 = (float2*)(ob + (size_t)cout0 * NPIX_ + nc);
            float2* p1 = (float2*)(ob + (size_t)(cout0 + 8) * NPIX_ + nc);
            *p0 = make_float2(acc[mi][ni][0], acc[mi][ni][1]);
            *p1 = make_float2(acc[mi][ni][2], acc[mi][ni][3]);
        }
    }
}

// ---------------------------------------------------------------------------
extern "C" void kernel_launch(void* const* d_in, const int* in_sizes, int n_in,
                              void* d_out, int out_size) {
    const float* x = (const float*)d_in[0];   // [32,256,64,64]
    const float* w = (const float*)d_in[1];   // [256,256,3,3]
    float* out = (float*)d_out;               // [32,256,32,32]

    cudaFuncSetAttribute(conv_fp16_kernel,
                         cudaFuncAttributeMaxDynamicSharedMemorySize, SMEM_TOTAL);

    transform_kernel<<<2304 + 32768, 256>>>(x, w);
    {
        dim3 grid(COUT_ / BM, (B_ * NPIX_) / BN);   // (2, 256)
        conv_fp16_kernel<<<grid, 256, SMEM_TOTAL>>>(out);
    }
}